// round 16
// baseline (speedup 1.0000x reference)
#include <cuda_runtime.h>
#include <cuda_bf16.h>
#include <cstdint>

#define NN   8192
#define DD   128
#define TILE 128
#define NT   (NN / TILE)           // 64
#define NTRI (NT * (NT + 1) / 2)   // 2080

// ---------------- smem layout: 2-stage pipelined K chunks of 32 -------------
// per-buf: [128 rows][40 bf16] -> 80B row stride (16B aligned; 8 consecutive
// rows hit distinct 16B segments mod 128 -> conflict-free ldmatrix)
#define T_ROWB      80
#define BUF_B       (TILE * T_ROWB)            // 10240
#define STAGE_B     (4 * BUF_B)                // 40960 (A_hi, A_lo, B_hi, B_lo)
#define AUX         (2 * STAGE_B)              // 81920
#define AUX_SQR     (AUX + 0)
#define AUX_SQC     (AUX + 512)
#define AUX_LR      (AUX + 1024)
#define AUX_LC      (AUX + 1536)
#define AUX_RMAX    (AUX + 2048)
#define AUX_RMIN    (AUX + 2560)
#define AUX_CMAX    (AUX + 3072)
#define AUX_CMIN    (AUX + 3584)
#define SMEM_BYTES  (AUX + 4096)               // 86016 -> 2 CTAs/SM

// ---------------- device scratch ----------------
__device__ unsigned      g_maxpos[NN];
__device__ unsigned      g_minneg[NN];
__device__ float         g_sq[NN];
__device__ int           g_lab[NN];
__device__ __nv_bfloat16 g_hi[NN * DD];
__device__ __nv_bfloat16 g_lo[NN * DD];

__device__ __forceinline__ uint32_t smem_u32(const void* p) {
    uint32_t a;
    asm("{ .reg .u64 t; cvta.to.shared.u64 t, %1; cvt.u32.u64 %0, t; }" : "=r"(a) : "l"(p));
    return a;
}
__device__ __forceinline__ void ldmx4(uint32_t* r, uint32_t addr) {
    asm volatile("ldmatrix.sync.aligned.m8n8.x4.shared.b16 {%0,%1,%2,%3}, [%4];"
                 : "=r"(r[0]), "=r"(r[1]), "=r"(r[2]), "=r"(r[3]) : "r"(addr));
}
__device__ __forceinline__ void mma16816(float* c, const uint32_t* a,
                                         uint32_t b0, uint32_t b1) {
    asm volatile(
        "mma.sync.aligned.m16n8k16.row.col.f32.bf16.bf16.f32 "
        "{%0,%1,%2,%3}, {%4,%5,%6,%7}, {%8,%9}, {%0,%1,%2,%3};"
        : "+f"(c[0]), "+f"(c[1]), "+f"(c[2]), "+f"(c[3])
        : "r"(a[0]), "r"(a[1]), "r"(a[2]), "r"(a[3]), "r"(b0), "r"(b1));
}
#define CP_ASYNC16(dst, src) \
    asm volatile("cp.async.cg.shared.global [%0], [%1], 16;" :: "r"(dst), "l"(src))
#define CP_COMMIT() asm volatile("cp.async.commit_group;" ::: "memory")
#define CP_WAIT(n)  asm volatile("cp.async.wait_group %0;" :: "n"(n) : "memory")

// ---------------------------------------------------------------------------
// Kernel 1: squared norms, labels, bf16 hi/lo split, scratch init. Warp/row.
// ---------------------------------------------------------------------------
__global__ void tl_init_kernel(const float* __restrict__ emb,
                               const int* __restrict__ lab) {
    int row  = (blockIdx.x * blockDim.x + threadIdx.x) >> 5;
    int lane = threadIdx.x & 31;
    if (row >= NN) return;
    float4 v = reinterpret_cast<const float4*>(emb + (size_t)row * DD)[lane];
    float s = v.x * v.x + v.y * v.y + v.z * v.z + v.w * v.w;

    float xs[4] = {v.x, v.y, v.z, v.w};
    __nv_bfloat16 hi[4], lo[4];
#pragma unroll
    for (int i = 0; i < 4; i++) {
        hi[i] = __float2bfloat16(xs[i]);
        lo[i] = __float2bfloat16(xs[i] - __bfloat162float(hi[i]));
    }
    size_t o = (size_t)row * DD + lane * 4;
    *reinterpret_cast<uint2*>(&g_hi[o]) = *reinterpret_cast<uint2*>(hi);
    *reinterpret_cast<uint2*>(&g_lo[o]) = *reinterpret_cast<uint2*>(lo);

#pragma unroll
    for (int off = 16; off > 0; off >>= 1) s += __shfl_xor_sync(0xffffffffu, s, off);
    if (lane == 0) {
        g_sq[row]     = s;
        g_lab[row]    = lab[row];
        g_maxpos[row] = 0u;
        g_minneg[row] = __float_as_uint(1e30f);
    }
}

// ---------------------------------------------------------------------------
// Kernel 2: one 128x128 triangular tile per CTA. 3-pass bf16 split GEMM on
// mma.sync.m16n8k16. K pipelined as 4 chunks of 32 with 2-stage double
// buffering (cp.async prefetch of chunk k+1 overlaps MMA on chunk k).
// Register-resident epilogue: d^2 + masks on C fragments, warp-shuffle
// reductions, smem max/min arrays, global uint atomics (symmetric tile
// serves both the row range and the col range).
// ---------------------------------------------------------------------------
__global__ void __launch_bounds__(256, 2)
tl_tile_mma() {
    extern __shared__ char smem[];
    const uint32_t sb = smem_u32(smem);
    const int tid = threadIdx.x, wid = tid >> 5, lane = tid & 31;

    // ---- triangular decode ----
    int idx = blockIdx.x;
    float disc = (float)((2 * NT + 1) * (2 * NT + 1)) - 8.0f * (float)idx;
    int r = (int)(((float)(2 * NT + 1) - sqrtf(disc)) * 0.5f);
    if (r < 0) r = 0;
    if (r > NT - 1) r = NT - 1;
    while (r > 0 && r * NT - r * (r - 1) / 2 > idx) r--;
    while ((r + 1) * NT - (r + 1) * r / 2 <= idx) r++;
    const int c = r + (idx - (r * NT - r * (r - 1) / 2));
    const int rowBase = r * TILE;
    const int colBase = c * TILE;

    // ---- prefetch chunk 0 into stage 0 ----
    // 2048 cp.async: buf(4) x row(128) x 16B-chunk(4); 8 per thread
#pragma unroll
    for (int it = 0; it < 8; it++) {
        int i = tid + it * 256;
        int buf = i >> 9, rc2 = i & 511, row = rc2 >> 2, ch = rc2 & 3;
        int base = (buf < 2) ? rowBase : colBase;
        const __nv_bfloat16* src = (buf & 1) ? g_lo : g_hi;
        const void* g = src + (size_t)(base + row) * DD + ch * 8;
        CP_ASYNC16(sb + buf * BUF_B + row * T_ROWB + ch * 16, g);
    }
    CP_COMMIT();

    if (tid < 128) {
        ((float*)(smem + AUX_SQR))[tid]      = g_sq[rowBase + tid];
        ((float*)(smem + AUX_SQC))[tid]      = g_sq[colBase + tid];
        ((int*)(smem + AUX_LR))[tid]         = g_lab[rowBase + tid];
        ((int*)(smem + AUX_LC))[tid]         = g_lab[colBase + tid];
        ((unsigned*)(smem + AUX_RMAX))[tid]  = 0u;
        ((unsigned*)(smem + AUX_RMIN))[tid]  = __float_as_uint(1e30f);
        ((unsigned*)(smem + AUX_CMAX))[tid]  = 0u;
        ((unsigned*)(smem + AUX_CMIN))[tid]  = __float_as_uint(1e30f);
    }

    // ---- warp tiling: warp (wm, wn) owns a 64x32 output block ----
    const int wm = wid >> 2, wn = wid & 3;
    float acc[4][4][4];
#pragma unroll
    for (int mb = 0; mb < 4; mb++)
#pragma unroll
        for (int nb = 0; nb < 4; nb++)
#pragma unroll
            for (int q = 0; q < 4; q++) acc[mb][nb][q] = 0.0f;

    // ldmatrix lane addressing (bytes within a tile buffer)
    const uint32_t a_off = (uint32_t)(wm * 64 + (lane & 15)) * T_ROWB
                         + ((lane >> 4) << 4);
    const uint32_t b_off = (uint32_t)(wn * 32 + (lane & 7) + ((lane >> 4) << 3)) * T_ROWB
                         + (((lane >> 3) & 1) << 4);

    // ---- pipelined K loop: 4 chunks of 32, 2 stages ----
#pragma unroll
    for (int kc = 0; kc < 4; kc++) {
        if (kc < 3) {   // prefetch next chunk into the other stage
            const uint32_t stb = sb + ((kc + 1) & 1) * STAGE_B;
#pragma unroll
            for (int it = 0; it < 8; it++) {
                int i = tid + it * 256;
                int buf = i >> 9, rc2 = i & 511, row = rc2 >> 2, ch = rc2 & 3;
                int base = (buf < 2) ? rowBase : colBase;
                const __nv_bfloat16* src = (buf & 1) ? g_lo : g_hi;
                const void* g = src + (size_t)(base + row) * DD + (kc + 1) * 32 + ch * 8;
                CP_ASYNC16(stb + buf * BUF_B + row * T_ROWB + ch * 16, g);
            }
            CP_COMMIT();
            CP_WAIT(1);   // chunk kc resident
        } else {
            CP_WAIT(0);
        }
        __syncthreads();

        const uint32_t st = sb + (kc & 1) * STAGE_B;
        const uint32_t a_hi_base = st + 0 * BUF_B + a_off;
        const uint32_t a_lo_base = st + 1 * BUF_B + a_off;
        const uint32_t b_hi_base = st + 2 * BUF_B + b_off;
        const uint32_t b_lo_base = st + 3 * BUF_B + b_off;
#pragma unroll
        for (int ks = 0; ks < 2; ks++) {
            uint32_t a[4][4], bh[2][4], bl[2][4];
            // pass 0: a_hi x b_hi
#pragma unroll
            for (int mb = 0; mb < 4; mb++)
                ldmx4(a[mb], a_hi_base + mb * (16 * T_ROWB) + ks * 32);
#pragma unroll
            for (int n2 = 0; n2 < 2; n2++)
                ldmx4(bh[n2], b_hi_base + n2 * (16 * T_ROWB) + ks * 32);
#pragma unroll
            for (int mb = 0; mb < 4; mb++)
#pragma unroll
                for (int nb = 0; nb < 4; nb++)
                    mma16816(acc[mb][nb], a[mb], bh[nb >> 1][(nb & 1) * 2],
                             bh[nb >> 1][(nb & 1) * 2 + 1]);
            // pass 1: a_hi x b_lo (reuse a)
#pragma unroll
            for (int n2 = 0; n2 < 2; n2++)
                ldmx4(bl[n2], b_lo_base + n2 * (16 * T_ROWB) + ks * 32);
#pragma unroll
            for (int mb = 0; mb < 4; mb++)
#pragma unroll
                for (int nb = 0; nb < 4; nb++)
                    mma16816(acc[mb][nb], a[mb], bl[nb >> 1][(nb & 1) * 2],
                             bl[nb >> 1][(nb & 1) * 2 + 1]);
            // pass 2: a_lo x b_hi (reuse bh, overwrite a)
#pragma unroll
            for (int mb = 0; mb < 4; mb++)
                ldmx4(a[mb], a_lo_base + mb * (16 * T_ROWB) + ks * 32);
#pragma unroll
            for (int mb = 0; mb < 4; mb++)
#pragma unroll
                for (int nb = 0; nb < 4; nb++)
                    mma16816(acc[mb][nb], a[mb], bh[nb >> 1][(nb & 1) * 2],
                             bh[nb >> 1][(nb & 1) * 2 + 1]);
        }
        __syncthreads();   // all warps done reading this stage before refill
    }

    // ---- register-resident epilogue ----
    // C fragment: acc[mb][nb][q]: row = wm*64 + mb*16 + (lane>>2) + 8*(q>=2)
    //                             col = wn*32 + nb*8 + 2*(lane&3) + (q&1)
    const float*    sqr  = (const float*)(smem + AUX_SQR);
    const float*    sqc  = (const float*)(smem + AUX_SQC);
    const int*      lr   = (const int*)(smem + AUX_LR);
    const int*      lc   = (const int*)(smem + AUX_LC);
    unsigned* sRowMax = (unsigned*)(smem + AUX_RMAX);
    unsigned* sRowMin = (unsigned*)(smem + AUX_RMIN);
    unsigned* sColMax = (unsigned*)(smem + AUX_CMAX);
    unsigned* sColMin = (unsigned*)(smem + AUX_CMIN);

    float sqc_r[8]; int lc_r[8], gcol[8];
#pragma unroll
    for (int nb = 0; nb < 4; nb++)
#pragma unroll
        for (int q2 = 0; q2 < 2; q2++) {
            int j  = nb * 2 + q2;
            int cl = wn * 32 + nb * 8 + 2 * (lane & 3) + q2;
            sqc_r[j] = sqc[cl];
            lc_r[j]  = lc[cl];
            gcol[j]  = colBase + cl;
        }
    float cpm[8], cnm[8];
#pragma unroll
    for (int j = 0; j < 8; j++) { cpm[j] = 0.0f; cnm[j] = 1e30f; }

#pragma unroll
    for (int mb = 0; mb < 4; mb++) {
        const int row0 = wm * 64 + mb * 16 + (lane >> 2);
        const int row1 = row0 + 8;
        const float sq0 = sqr[row0], sq1 = sqr[row1];
        const int   l0  = lr[row0],  l1  = lr[row1];
        const int   gr0 = rowBase + row0, gr1 = rowBase + row1;
        float rp0 = 0.0f, rn0 = 1e30f, rp1 = 0.0f, rn1 = 1e30f;
#pragma unroll
        for (int nb = 0; nb < 4; nb++) {
#pragma unroll
            for (int q = 0; q < 4; q++) {
                const int   j   = nb * 2 + (q & 1);
                const bool  hi2 = (q >= 2);
                const float sqi = hi2 ? sq1 : sq0;
                const int   li  = hi2 ? l1 : l0;
                const int   gri = hi2 ? gr1 : gr0;
                float d2 = fmaxf(sqi + sqc_r[j] - 2.0f * acc[mb][nb][q], 0.0f);
                if (li == lc_r[j]) {
                    if (gri != gcol[j]) {
                        if (hi2) rp1 = fmaxf(rp1, d2); else rp0 = fmaxf(rp0, d2);
                        cpm[j] = fmaxf(cpm[j], d2);
                    }
                } else {
                    if (hi2) rn1 = fminf(rn1, d2); else rn0 = fminf(rn0, d2);
                    cnm[j] = fminf(cnm[j], d2);
                }
            }
        }
#pragma unroll
        for (int o = 1; o <= 2; o <<= 1) {
            rp0 = fmaxf(rp0, __shfl_xor_sync(0xffffffffu, rp0, o));
            rn0 = fminf(rn0, __shfl_xor_sync(0xffffffffu, rn0, o));
            rp1 = fmaxf(rp1, __shfl_xor_sync(0xffffffffu, rp1, o));
            rn1 = fminf(rn1, __shfl_xor_sync(0xffffffffu, rn1, o));
        }
        if ((lane & 3) == 0) {
            atomicMax(&sRowMax[row0], __float_as_uint(rp0));
            atomicMin(&sRowMin[row0], __float_as_uint(rn0));
            atomicMax(&sRowMax[row1], __float_as_uint(rp1));
            atomicMin(&sRowMin[row1], __float_as_uint(rn1));
        }
    }

#pragma unroll
    for (int o = 4; o <= 16; o <<= 1)
#pragma unroll
        for (int j = 0; j < 8; j++) {
            cpm[j] = fmaxf(cpm[j], __shfl_xor_sync(0xffffffffu, cpm[j], o));
            cnm[j] = fminf(cnm[j], __shfl_xor_sync(0xffffffffu, cnm[j], o));
        }
    if (lane < 4) {
#pragma unroll
        for (int nb = 0; nb < 4; nb++)
#pragma unroll
            for (int q2 = 0; q2 < 2; q2++) {
                int j  = nb * 2 + q2;
                int cl = wn * 32 + nb * 8 + 2 * lane + q2;
                atomicMax(&sColMax[cl], __float_as_uint(cpm[j]));
                atomicMin(&sColMin[cl], __float_as_uint(cnm[j]));
            }
    }
    __syncthreads();

    if (tid < 128) {
        atomicMax(&g_maxpos[rowBase + tid], sRowMax[tid]);
        atomicMin(&g_minneg[rowBase + tid], sRowMin[tid]);
    } else {
        int t = tid - 128;
        atomicMax(&g_maxpos[colBase + t], sColMax[t]);
        atomicMin(&g_minneg[colBase + t], sColMin[t]);
    }
}

// ---------------------------------------------------------------------------
// Kernel 3: per-row sqrt + hinge, mean over N.
// ---------------------------------------------------------------------------
__global__ void tl_final_kernel(const float* __restrict__ margin_ptr,
                                float* __restrict__ out) {
    const float m = *margin_ptr;
    float sum = 0.0f;
    for (int r = threadIdx.x; r < NN; r += 256) {
        float pos = sqrtf(__uint_as_float(g_maxpos[r]));
        float neg = sqrtf(__uint_as_float(g_minneg[r]));
        sum += fmaxf(pos - neg + m, 0.0f);
    }
    __shared__ float red[256];
    red[threadIdx.x] = sum;
    __syncthreads();
    for (int s = 128; s > 0; s >>= 1) {
        if (threadIdx.x < s) red[threadIdx.x] += red[threadIdx.x + s];
        __syncthreads();
    }
    if (threadIdx.x == 0) out[0] = red[0] / (float)NN;
}

// ---------------------------------------------------------------------------
extern "C" void kernel_launch(void* const* d_in, const int* in_sizes, int n_in,
                              void* d_out, int out_size) {
    const float* emb    = (const float*)d_in[0];
    const int*   labels = (const int*)d_in[1];
    const float* margin = (const float*)d_in[2];
    float*       out    = (float*)d_out;

    cudaFuncSetAttribute(tl_tile_mma, cudaFuncAttributeMaxDynamicSharedMemorySize,
                         SMEM_BYTES);

    tl_init_kernel<<<NN / 8, 256>>>(emb, labels);
    tl_tile_mma<<<NTRI, 256, SMEM_BYTES>>>();
    tl_final_kernel<<<1, 256>>>(margin, out);
}